// round 15
// baseline (speedup 1.0000x reference)
#include <cuda_runtime.h>

#define NN 512          // nodes
#define C1 36
#define C2 24
#define C3 8
#define EMAX (NN * NN)
#define EB_MAX (EMAX / 256)   // 1024

typedef unsigned long long u64;

// ---- scratch (device globals; no allocs allowed) ----
__device__ __align__(16) float g_h1[NN * C1];
__device__ __align__(16) float g_h2[NN * C2];
__device__ __align__(16) float g_h3[NN * C3];
__device__ int g_cnt[NN];
__device__ int g_off[NN + 1];
__device__ int g_bcntT[NN * EB_MAX];         // TRANSPOSED: [d * EB + b]
__device__ int g_ssrc[EMAX];                 // src in dst-sorted order
__device__ __align__(16) float4 g_ea[EMAX];  // edge_attr in dst-sorted order
__device__ int g_done;

// ---- f32x2 packed helpers (sm_100a) ----
__device__ __forceinline__ u64 pk(float lo, float hi) {
    u64 r; asm("mov.b64 %0, {%1,%2};" : "=l"(r) : "f"(lo), "f"(hi)); return r;
}
__device__ __forceinline__ void upk(u64 v, float& lo, float& hi) {
    asm("mov.b64 {%0,%1}, %2;" : "=f"(lo), "=f"(hi) : "l"(v));
}
__device__ __forceinline__ u64 fma2(u64 a, u64 b, u64 c) {
    u64 d; asm("fma.rn.f32x2 %0, %1, %2, %3;" : "=l"(d) : "l"(a), "l"(b), "l"(c)); return d;
}
__device__ __forceinline__ u64 relu2(u64 v) {
    u64 r;
    asm("{\n\t.reg .f32 lo, hi;\n\t"
        "mov.b64 {lo, hi}, %1;\n\t"
        "max.f32 lo, lo, 0f00000000;\n\t"
        "max.f32 hi, hi, 0f00000000;\n\t"
        "mov.b64 %0, {lo, hi};\n\t}"
        : "=l"(r) : "l"(v));
    return r;
}
__device__ __forceinline__ u64 d2u(double d) { return __double_as_longlong(d); }

__device__ __forceinline__ int eidx(const void* ei, int is64, int pos) {
    int v = is64 ? (int)((const long long*)ei)[pos] : ((const int*)ei)[pos];
    return v & (NN - 1);
}

// in-block dtype detect: first 64 int64 values all in [0,NN) => int64
__device__ __forceinline__ int detect64(const void* ei, int t, int* bad) {
    if (t == 0) *bad = 0;
    __syncthreads();
    if (t < 64) {
        long long v = ((const long long*)ei)[t];
        if (v < 0 || v >= NN) atomicOr(bad, 1);
    }
    __syncthreads();
    return !(*bad);
}

// ---------------- per-block dst histogram (transposed store) + detect + g_done reset ----------------
__global__ __launch_bounds__(256) void k_bhist(const void* __restrict__ ei, int E, int EB) {
    __shared__ int s[NN];
    __shared__ int bad;
    int t = threadIdx.x, b = blockIdx.x;
    s[t] = 0; s[t + 256] = 0;
    int is64 = detect64(ei, t, &bad);
    __syncthreads();
    if (b == 0 && t == 0) g_done = 0;
    int e = b * 256 + t;
    if (e < E) atomicAdd(&s[eidx(ei, is64, E + e)], 1);
    __syncthreads();
    g_bcntT[t * EB + b] = s[t];
    g_bcntT[(t + 256) * EB + b] = s[t + 256];
}

// ---------------- per-dst exclusive scan over blocks; last block computes g_off ----------------
__global__ __launch_bounds__(256) void k_bscan(int EB) {
    int d = blockIdx.x, t = threadIdx.x;
    int base = d * EB;
    int b0 = 4 * t;
    int v0 = 0, v1 = 0, v2 = 0, v3 = 0;
    if (b0 + 0 < EB) v0 = g_bcntT[base + b0 + 0];
    if (b0 + 1 < EB) v1 = g_bcntT[base + b0 + 1];
    if (b0 + 2 < EB) v2 = g_bcntT[base + b0 + 2];
    if (b0 + 3 < EB) v3 = g_bcntT[base + b0 + 3];
    int sum = v0 + v1 + v2 + v3;
    int lane = t & 31, w = t >> 5;
    int inc = sum;
#pragma unroll
    for (int off = 1; off < 32; off <<= 1) {
        int x = __shfl_up_sync(0xffffffffu, inc, off);
        if (lane >= off) inc += x;
    }
    __shared__ int wsum[8];
    if (lane == 31) wsum[w] = inc;
    __syncthreads();
    if (w == 0 && lane < 8) {
        int x = wsum[lane];
#pragma unroll
        for (int off = 1; off < 8; off <<= 1) {
            int y = __shfl_up_sync(0xffu, x, off);
            if (lane >= off) x += y;
        }
        wsum[lane] = x;
    }
    __syncthreads();
    int excl = inc - sum + (w ? wsum[w - 1] : 0);
    if (b0 + 0 < EB) g_bcntT[base + b0 + 0] = excl;
    if (b0 + 1 < EB) g_bcntT[base + b0 + 1] = excl + v0;
    if (b0 + 2 < EB) g_bcntT[base + b0 + 2] = excl + v0 + v1;
    if (b0 + 3 < EB) g_bcntT[base + b0 + 3] = excl + v0 + v1 + v2;
    if (t == 255) g_cnt[d] = excl + sum;

    // last block computes node offsets g_off[0..NN]
    __threadfence();
    __shared__ int isLast;
    if (t == 0) isLast = (atomicAdd(&g_done, 1) == NN - 1);
    __syncthreads();
    if (!isLast) return;
    __threadfence();
    int a0 = g_cnt[2 * t], a1 = g_cnt[2 * t + 1];
    int ts = a0 + a1;
    int inc2 = ts;
#pragma unroll
    for (int off = 1; off < 32; off <<= 1) {
        int x = __shfl_up_sync(0xffffffffu, inc2, off);
        if (lane >= off) inc2 += x;
    }
    if (lane == 31) wsum[w] = inc2;
    __syncthreads();
    if (w == 0 && lane < 8) {
        int x = wsum[lane];
#pragma unroll
        for (int off = 1; off < 8; off <<= 1) {
            int y = __shfl_up_sync(0xffu, x, off);
            if (lane >= off) x += y;
        }
        wsum[lane] = x;
    }
    __syncthreads();
    int ex2 = inc2 - ts + (w ? wsum[w - 1] : 0);
    g_off[2 * t + 1] = ex2 + a0;
    g_off[2 * t + 2] = ex2 + a0 + a1;
    if (t == 0) g_off[0] = 0;
}

// ---------------- placement: deterministic offsets, smem-only atomics ----------------
__global__ __launch_bounds__(256) void k_place(const void* __restrict__ ei,
                                               const float4* __restrict__ ea, int E, int EB) {
    __shared__ int s[NN];
    __shared__ int bad;
    int t = threadIdx.x, b = blockIdx.x;
    s[t] = 0; s[t + 256] = 0;
    int is64 = detect64(ei, t, &bad);
    __syncthreads();
    int e = b * 256 + t;
    if (e < E) {
        int src = eidx(ei, is64, e);
        int d = eidx(ei, is64, E + e);
        int r = atomicAdd(&s[d], 1);
        int pos = g_off[d] + g_bcntT[d * EB + b] + r;
        g_ssrc[pos] = src;
        g_ea[pos] = ea[e];
    }
}

// ---------------- layer 1: cin=1, cout=36, packed, 3-edge, 128 thr ----------------
#define P1 (C1 / 2)
__global__ __launch_bounds__(128, 4) void k_layer1(
    const float* __restrict__ x, const float* __restrict__ W, const float* __restrict__ b,
    const float* __restrict__ root, const float* __restrict__ bias)
{
    __shared__ double2 Wp[P1][2];
    __shared__ u64 Bp[P1];
    __shared__ float parts[4][C1];
    __shared__ float xn;
    int n = blockIdx.x, t = threadIdx.x;
    if (t < P1) {
        int c0 = 2 * t;
        Wp[t][0] = make_double2(
            __longlong_as_double(pk(W[c0], W[c0 + 1])),
            __longlong_as_double(pk(W[C1 + c0], W[C1 + c0 + 1])));
        Wp[t][1] = make_double2(
            __longlong_as_double(pk(W[2 * C1 + c0], W[2 * C1 + c0 + 1])),
            __longlong_as_double(pk(W[3 * C1 + c0], W[3 * C1 + c0 + 1])));
        Bp[t] = pk(b[c0], b[c0 + 1]);
    }
    if (t == 0) xn = x[n];
    __syncthreads();
    int beg = g_off[n], end = g_off[n + 1];
    u64 acc2[P1];
#pragma unroll
    for (int o = 0; o < P1; o++) acc2[o] = 0ull;
    for (int p = beg + t; p < end; p += 384) {
        int pe[3] = {p, p + 128, p + 256};
        u64 ax[3], ay[3], az[3], aw[3], xi[3];
#pragma unroll
        for (int e = 0; e < 3; e++) {
            bool ok = pe[e] < end;
            int pp = ok ? pe[e] : p;
            float4 a = g_ea[pp];
            float xs = ok ? __ldg(x + g_ssrc[pp]) : 0.f;
            ax[e] = pk(a.x, a.x); ay[e] = pk(a.y, a.y);
            az[e] = pk(a.z, a.z); aw[e] = pk(a.w, a.w);
            xi[e] = pk(xs, xs);
        }
#pragma unroll
        for (int op = 0; op < P1; op++) {
            double2 d0 = Wp[op][0];
            double2 d1 = Wp[op][1];
            u64 w0 = d2u(d0.x), w1 = d2u(d0.y), w2 = d2u(d1.x), w3 = d2u(d1.y);
            u64 bb = Bp[op];
#pragma unroll
            for (int e = 0; e < 3; e++) {
                u64 v = fma2(ax[e], w0, bb);
                v = fma2(ay[e], w1, v);
                v = fma2(az[e], w2, v);
                v = fma2(aw[e], w3, v);
                acc2[op] = fma2(xi[e], relu2(v), acc2[op]);
            }
        }
    }
    float acc[C1];
#pragma unroll
    for (int op = 0; op < P1; op++) upk(acc2[op], acc[2 * op], acc[2 * op + 1]);
#pragma unroll
    for (int o = 0; o < C1; o++)
#pragma unroll
        for (int off = 16; off; off >>= 1)
            acc[o] += __shfl_down_sync(0xffffffffu, acc[o], off);
    int wid = t >> 5, lane = t & 31;
    if (lane == 0)
#pragma unroll
        for (int o = 0; o < C1; o++) parts[wid][o] = acc[o];
    __syncthreads();
    if (t < C1) {
        float s = parts[0][t] + parts[1][t] + parts[2][t] + parts[3][t];
        float cnt = fmaxf((float)(end - beg), 1.f);
        float v = s / cnt + bias[t] + xn * root[t];
        g_h1[n * C1 + t] = fmaxf(v, 0.f);
    }
}

// ---------------- layer 2: cin=36, cout=24, packed, 3-edge, 128 thr ----------------
#define P2 (C2 / 2)
#define W2PAIRS (C1 * P2)
__global__ __launch_bounds__(128, 4) void k_layer2(
    const float* __restrict__ W, const float* __restrict__ b,
    const float* __restrict__ root, const float* __restrict__ bias)
{
    __shared__ double2 WpA[W2PAIRS][2];
    __shared__ u64 WpB[W2PAIRS];
    __shared__ float hprev[C1];
    __shared__ float rootS[C1 * C2];
    __shared__ float parts[4][C2];
    int n = blockIdx.x, t = threadIdx.x;
    for (int idx = t; idx < W2PAIRS; idx += 128) {
        int i = idx / P2, op = idx % P2;
        int c0 = i * C2 + 2 * op;
        WpA[idx][0] = make_double2(
            __longlong_as_double(pk(W[c0], W[c0 + 1])),
            __longlong_as_double(pk(W[864 + c0], W[864 + c0 + 1])));
        WpA[idx][1] = make_double2(
            __longlong_as_double(pk(W[1728 + c0], W[1728 + c0 + 1])),
            __longlong_as_double(pk(W[2592 + c0], W[2592 + c0 + 1])));
        WpB[idx] = pk(b[c0], b[c0 + 1]);
    }
    if (t < C1) hprev[t] = g_h1[n * C1 + t];
    for (int idx = t; idx < C1 * C2; idx += 128) rootS[idx] = root[idx];
    __syncthreads();
    int beg = g_off[n], end = g_off[n + 1];
    u64 acc2[P2];
#pragma unroll
    for (int o = 0; o < P2; o++) acc2[o] = 0ull;
    for (int p = beg + t; p < end; p += 384) {
        int pe[3] = {p, p + 128, p + 256};
        u64 ax[3], ay[3], az[3], aw[3];
        const float4* hp[3];
        float mk[3];
#pragma unroll
        for (int e = 0; e < 3; e++) {
            bool ok = pe[e] < end;
            int pp = ok ? pe[e] : p;
            float4 a = g_ea[pp];
            ax[e] = pk(a.x, a.x); ay[e] = pk(a.y, a.y);
            az[e] = pk(a.z, a.z); aw[e] = pk(a.w, a.w);
            hp[e] = (const float4*)(g_h1 + g_ssrc[pp] * C1);
            mk[e] = ok ? 1.f : 0.f;
        }
#pragma unroll 1
        for (int q = 0; q < C1 / 4; q++) {
            float f[3][4];
#pragma unroll
            for (int e = 0; e < 3; e++) {
                float4 v = __ldg(hp[e] + q);
                f[e][0] = v.x * mk[e]; f[e][1] = v.y * mk[e];
                f[e][2] = v.z * mk[e]; f[e][3] = v.w * mk[e];
            }
#pragma unroll
            for (int j = 0; j < 4; j++) {
                int base = (4 * q + j) * P2;
                u64 xi[3];
#pragma unroll
                for (int e = 0; e < 3; e++) xi[e] = pk(f[e][j], f[e][j]);
#pragma unroll
                for (int op = 0; op < P2; op++) {
                    double2 d0 = WpA[base + op][0];
                    double2 d1 = WpA[base + op][1];
                    u64 w0 = d2u(d0.x), w1 = d2u(d0.y), w2 = d2u(d1.x), w3 = d2u(d1.y);
                    u64 bb = WpB[base + op];
#pragma unroll
                    for (int e = 0; e < 3; e++) {
                        u64 v = fma2(ax[e], w0, bb);
                        v = fma2(ay[e], w1, v);
                        v = fma2(az[e], w2, v);
                        v = fma2(aw[e], w3, v);
                        acc2[op] = fma2(xi[e], relu2(v), acc2[op]);
                    }
                }
            }
        }
    }
    float acc[C2];
#pragma unroll
    for (int op = 0; op < P2; op++) upk(acc2[op], acc[2 * op], acc[2 * op + 1]);
#pragma unroll
    for (int o = 0; o < C2; o++)
#pragma unroll
        for (int off = 16; off; off >>= 1)
            acc[o] += __shfl_down_sync(0xffffffffu, acc[o], off);
    int wid = t >> 5, lane = t & 31;
    if (lane == 0)
#pragma unroll
        for (int o = 0; o < C2; o++) parts[wid][o] = acc[o];
    __syncthreads();
    if (t < C2) {
        float s = parts[0][t] + parts[1][t] + parts[2][t] + parts[3][t];
        float cnt = fmaxf((float)(end - beg), 1.f);
        float v = s / cnt + bias[t];
#pragma unroll
        for (int i = 0; i < C1; i++) v = fmaf(hprev[i], rootS[i * C2 + t], v);
        g_h2[n * C2 + t] = fmaxf(v, 0.f);
    }
}

// ---------------- layer 3: cin=24, cout=8, packed, 3-edge, 128 thr ----------------
#define P3 (C3 / 2)
#define W3PAIRS (C2 * P3)
__global__ __launch_bounds__(128, 4) void k_layer3(
    const float* __restrict__ W, const float* __restrict__ b,
    const float* __restrict__ root, const float* __restrict__ bias)
{
    __shared__ double2 WpA[W3PAIRS][2];
    __shared__ u64 WpB[W3PAIRS];
    __shared__ float hprev[C2];
    __shared__ float rootS[C2 * C3];
    __shared__ float parts[4][C3];
    int n = blockIdx.x, t = threadIdx.x;
    if (t < W3PAIRS) {
        int i = t / P3, op = t % P3;
        int c0 = i * C3 + 2 * op;
        WpA[t][0] = make_double2(
            __longlong_as_double(pk(W[c0], W[c0 + 1])),
            __longlong_as_double(pk(W[192 + c0], W[192 + c0 + 1])));
        WpA[t][1] = make_double2(
            __longlong_as_double(pk(W[384 + c0], W[384 + c0 + 1])),
            __longlong_as_double(pk(W[576 + c0], W[576 + c0 + 1])));
        WpB[t] = pk(b[c0], b[c0 + 1]);
    }
    if (t < C2) hprev[t] = g_h2[n * C2 + t];
    for (int idx = t; idx < C2 * C3; idx += 128) rootS[idx] = root[idx];
    __syncthreads();
    int beg = g_off[n], end = g_off[n + 1];
    u64 acc2[P3];
#pragma unroll
    for (int o = 0; o < P3; o++) acc2[o] = 0ull;
    for (int p = beg + t; p < end; p += 384) {
        int pe[3] = {p, p + 128, p + 256};
        u64 ax[3], ay[3], az[3], aw[3];
        const float4* hp[3];
        float mk[3];
#pragma unroll
        for (int e = 0; e < 3; e++) {
            bool ok = pe[e] < end;
            int pp = ok ? pe[e] : p;
            float4 a = g_ea[pp];
            ax[e] = pk(a.x, a.x); ay[e] = pk(a.y, a.y);
            az[e] = pk(a.z, a.z); aw[e] = pk(a.w, a.w);
            hp[e] = (const float4*)(g_h2 + g_ssrc[pp] * C2);
            mk[e] = ok ? 1.f : 0.f;
        }
#pragma unroll 1
        for (int q = 0; q < C2 / 4; q++) {
            float f[3][4];
#pragma unroll
            for (int e = 0; e < 3; e++) {
                float4 v = __ldg(hp[e] + q);
                f[e][0] = v.x * mk[e]; f[e][1] = v.y * mk[e];
                f[e][2] = v.z * mk[e]; f[e][3] = v.w * mk[e];
            }
#pragma unroll
            for (int j = 0; j < 4; j++) {
                int base = (4 * q + j) * P3;
                u64 xi[3];
#pragma unroll
                for (int e = 0; e < 3; e++) xi[e] = pk(f[e][j], f[e][j]);
#pragma unroll
                for (int op = 0; op < P3; op++) {
                    double2 d0 = WpA[base + op][0];
                    double2 d1 = WpA[base + op][1];
                    u64 w0 = d2u(d0.x), w1 = d2u(d0.y), w2 = d2u(d1.x), w3 = d2u(d1.y);
                    u64 bb = WpB[base + op];
#pragma unroll
                    for (int e = 0; e < 3; e++) {
                        u64 v = fma2(ax[e], w0, bb);
                        v = fma2(ay[e], w1, v);
                        v = fma2(az[e], w2, v);
                        v = fma2(aw[e], w3, v);
                        acc2[op] = fma2(xi[e], relu2(v), acc2[op]);
                    }
                }
            }
        }
    }
    float acc[C3];
#pragma unroll
    for (int op = 0; op < P3; op++) upk(acc2[op], acc[2 * op], acc[2 * op + 1]);
#pragma unroll
    for (int o = 0; o < C3; o++)
#pragma unroll
        for (int off = 16; off; off >>= 1)
            acc[o] += __shfl_down_sync(0xffffffffu, acc[o], off);
    int wid = t >> 5, lane = t & 31;
    if (lane == 0)
#pragma unroll
        for (int o = 0; o < C3; o++) parts[wid][o] = acc[o];
    __syncthreads();
    if (t < C3) {
        float s = parts[0][t] + parts[1][t] + parts[2][t] + parts[3][t];
        float cnt = fmaxf((float)(end - beg), 1.f);
        float v = s / cnt + bias[t];
#pragma unroll
        for (int i = 0; i < C2; i++) v = fmaf(hprev[i], rootS[i * C3 + t], v);
        g_h3[n * C3 + t] = fmaxf(v, 0.f);
    }
}

// ---------------- CBT: out[i,j] = sum_d |h3[j,d]-h3[i,d]| ----------------
__global__ void k_cbt(float* __restrict__ out) {
    __shared__ float hs[NN * C3];
    int t = threadIdx.x;
    for (int idx = t; idx < NN * C3; idx += blockDim.x) hs[idx] = g_h3[idx];
    __syncthreads();
    int i = blockIdx.x;
    float hi[C3];
#pragma unroll
    for (int d = 0; d < C3; d++) hi[d] = hs[i * C3 + d];
    float s = 0.f;
#pragma unroll
    for (int d = 0; d < C3; d++) s += fabsf(hs[t * C3 + d] - hi[d]);
    out[i * NN + t] = s;
}

extern "C" void kernel_launch(void* const* d_in, const int* in_sizes, int n_in,
                              void* d_out, int out_size) {
    const float* x  = (const float*)d_in[0];
    const float4* ea = (const float4*)d_in[1];
    const void* ei = d_in[2];
    const float* W1 = (const float*)d_in[3];
    const float* b1 = (const float*)d_in[4];
    const float* r1 = (const float*)d_in[5];
    const float* B1 = (const float*)d_in[6];
    const float* W2 = (const float*)d_in[7];
    const float* b2 = (const float*)d_in[8];
    const float* r2 = (const float*)d_in[9];
    const float* B2 = (const float*)d_in[10];
    const float* W3 = (const float*)d_in[11];
    const float* b3 = (const float*)d_in[12];
    const float* r3 = (const float*)d_in[13];
    const float* B3 = (const float*)d_in[14];
    float* out = (float*)d_out;

    int E = in_sizes[2] / 2;
    if (E > EMAX) E = EMAX;
    int EB = (E + 255) / 256;

    k_bhist<<<EB, 256>>>(ei, E, EB);
    k_bscan<<<NN, 256>>>(EB);
    k_place<<<EB, 256>>>(ei, ea, E, EB);

    k_layer1<<<NN, 128>>>(x, W1, b1, r1, B1);
    k_layer2<<<NN, 128>>>(W2, b2, r2, B2);
    k_layer3<<<NN, 128>>>(W3, b3, r3, B3);

    k_cbt<<<NN, NN>>>(out);
}

// round 16
// speedup vs baseline: 1.1247x; 1.1247x over previous
#include <cuda_runtime.h>

#define NN 512          // nodes
#define C1 36
#define C2 24
#define C3 8
#define EMAX (NN * NN)
#define EPB 1024                   // edges per prep block
#define EB_MAX (EMAX / EPB)        // 256

typedef unsigned long long u64;

// ---- scratch (device globals; no allocs allowed) ----
__device__ __align__(16) float g_h1[NN * C1];
__device__ __align__(16) float g_h2[NN * C2];
__device__ __align__(16) float g_h3[NN * C3];
__device__ int g_cnt[NN];
__device__ int g_off[NN + 1];
__device__ int g_bcntT[NN * EB_MAX];         // TRANSPOSED: [d * EB + b]
__device__ int g_ssrc[EMAX];                 // src in dst-sorted order
__device__ __align__(16) float4 g_ea[EMAX];  // edge_attr in dst-sorted order
__device__ int g_done;

// ---- f32x2 packed helpers (sm_100a) ----
__device__ __forceinline__ u64 pk(float lo, float hi) {
    u64 r; asm("mov.b64 %0, {%1,%2};" : "=l"(r) : "f"(lo), "f"(hi)); return r;
}
__device__ __forceinline__ void upk(u64 v, float& lo, float& hi) {
    asm("mov.b64 {%0,%1}, %2;" : "=f"(lo), "=f"(hi) : "l"(v));
}
__device__ __forceinline__ u64 fma2(u64 a, u64 b, u64 c) {
    u64 d; asm("fma.rn.f32x2 %0, %1, %2, %3;" : "=l"(d) : "l"(a), "l"(b), "l"(c)); return d;
}
__device__ __forceinline__ u64 relu2(u64 v) {
    u64 r;
    asm("{\n\t.reg .f32 lo, hi;\n\t"
        "mov.b64 {lo, hi}, %1;\n\t"
        "max.f32 lo, lo, 0f00000000;\n\t"
        "max.f32 hi, hi, 0f00000000;\n\t"
        "mov.b64 %0, {lo, hi};\n\t}"
        : "=l"(r) : "l"(v));
    return r;
}
__device__ __forceinline__ u64 d2u(double d) { return __double_as_longlong(d); }

__device__ __forceinline__ int eidx(const void* ei, int is64, int pos) {
    int v = is64 ? (int)((const long long*)ei)[pos] : ((const int*)ei)[pos];
    return v & (NN - 1);
}

// in-block dtype detect: first 64 int64 values all in [0,NN) => int64
__device__ __forceinline__ int detect64(const void* ei, int t, int* bad) {
    if (t == 0) *bad = 0;
    __syncthreads();
    if (t < 64) {
        long long v = ((const long long*)ei)[t];
        if (v < 0 || v >= NN) atomicOr(bad, 1);
    }
    __syncthreads();
    return !(*bad);
}

// ---------------- per-block dst histogram: 1024 edges/block, transposed store ----------------
__global__ __launch_bounds__(256) void k_bhist(const void* __restrict__ ei, int E, int EB) {
    __shared__ int s[NN];
    __shared__ int bad;
    int t = threadIdx.x, b = blockIdx.x;
    s[t] = 0; s[t + 256] = 0;
    int is64 = detect64(ei, t, &bad);
    __syncthreads();
    if (b == 0 && t == 0) g_done = 0;
#pragma unroll
    for (int k = 0; k < 4; k++) {
        int e = b * EPB + k * 256 + t;
        if (e < E) atomicAdd(&s[eidx(ei, is64, E + e)], 1);
    }
    __syncthreads();
    g_bcntT[t * EB + b] = s[t];
    g_bcntT[(t + 256) * EB + b] = s[t + 256];
}

// ---------------- per-dst exclusive scan over blocks; last block computes g_off ----------------
__global__ __launch_bounds__(256) void k_bscan(int EB) {
    int d = blockIdx.x, t = threadIdx.x;
    int base = d * EB;
    int b0 = 4 * t;
    int v0 = 0, v1 = 0, v2 = 0, v3 = 0;
    if (b0 + 0 < EB) v0 = g_bcntT[base + b0 + 0];
    if (b0 + 1 < EB) v1 = g_bcntT[base + b0 + 1];
    if (b0 + 2 < EB) v2 = g_bcntT[base + b0 + 2];
    if (b0 + 3 < EB) v3 = g_bcntT[base + b0 + 3];
    int sum = v0 + v1 + v2 + v3;
    int lane = t & 31, w = t >> 5;
    int inc = sum;
#pragma unroll
    for (int off = 1; off < 32; off <<= 1) {
        int x = __shfl_up_sync(0xffffffffu, inc, off);
        if (lane >= off) inc += x;
    }
    __shared__ int wsum[8];
    if (lane == 31) wsum[w] = inc;
    __syncthreads();
    if (w == 0 && lane < 8) {
        int x = wsum[lane];
#pragma unroll
        for (int off = 1; off < 8; off <<= 1) {
            int y = __shfl_up_sync(0xffu, x, off);
            if (lane >= off) x += y;
        }
        wsum[lane] = x;
    }
    __syncthreads();
    int excl = inc - sum + (w ? wsum[w - 1] : 0);
    if (b0 + 0 < EB) g_bcntT[base + b0 + 0] = excl;
    if (b0 + 1 < EB) g_bcntT[base + b0 + 1] = excl + v0;
    if (b0 + 2 < EB) g_bcntT[base + b0 + 2] = excl + v0 + v1;
    if (b0 + 3 < EB) g_bcntT[base + b0 + 3] = excl + v0 + v1 + v2;
    if (t == 255) g_cnt[d] = excl + sum;

    // last block computes node offsets g_off[0..NN]
    __threadfence();
    __shared__ int isLast;
    if (t == 0) isLast = (atomicAdd(&g_done, 1) == NN - 1);
    __syncthreads();
    if (!isLast) return;
    __threadfence();
    int a0 = g_cnt[2 * t], a1 = g_cnt[2 * t + 1];
    int ts = a0 + a1;
    int inc2 = ts;
#pragma unroll
    for (int off = 1; off < 32; off <<= 1) {
        int x = __shfl_up_sync(0xffffffffu, inc2, off);
        if (lane >= off) inc2 += x;
    }
    if (lane == 31) wsum[w] = inc2;
    __syncthreads();
    if (w == 0 && lane < 8) {
        int x = wsum[lane];
#pragma unroll
        for (int off = 1; off < 8; off <<= 1) {
            int y = __shfl_up_sync(0xffu, x, off);
            if (lane >= off) x += y;
        }
        wsum[lane] = x;
    }
    __syncthreads();
    int ex2 = inc2 - ts + (w ? wsum[w - 1] : 0);
    g_off[2 * t + 1] = ex2 + a0;
    g_off[2 * t + 2] = ex2 + a0 + a1;
    if (t == 0) g_off[0] = 0;
}

// ---------------- placement: 1024 edges/block, deterministic offsets, smem atomics ----------------
__global__ __launch_bounds__(256) void k_place(const void* __restrict__ ei,
                                               const float4* __restrict__ ea, int E, int EB) {
    __shared__ int s[NN];
    __shared__ int bad;
    int t = threadIdx.x, b = blockIdx.x;
    s[t] = 0; s[t + 256] = 0;
    int is64 = detect64(ei, t, &bad);
    __syncthreads();
#pragma unroll
    for (int k = 0; k < 4; k++) {
        int e = b * EPB + k * 256 + t;
        if (e < E) {
            int src = eidx(ei, is64, e);
            int d = eidx(ei, is64, E + e);
            int r = atomicAdd(&s[d], 1);
            int pos = g_off[d] + g_bcntT[d * EB + b] + r;
            g_ssrc[pos] = src;
            g_ea[pos] = ea[e];
        }
    }
}

// ---------------- layer 1: cin=1, cout=36, packed, 2-edge, 128 thr (R12 config) ----------------
#define P1 (C1 / 2)
__global__ __launch_bounds__(128, 4) void k_layer1(
    const float* __restrict__ x, const float* __restrict__ W, const float* __restrict__ b,
    const float* __restrict__ root, const float* __restrict__ bias)
{
    __shared__ double2 Wp[P1][2];
    __shared__ u64 Bp[P1];
    __shared__ float parts[4][C1];
    __shared__ float xn;
    int n = blockIdx.x, t = threadIdx.x;
    if (t < P1) {
        int c0 = 2 * t;
        Wp[t][0] = make_double2(
            __longlong_as_double(pk(W[c0], W[c0 + 1])),
            __longlong_as_double(pk(W[C1 + c0], W[C1 + c0 + 1])));
        Wp[t][1] = make_double2(
            __longlong_as_double(pk(W[2 * C1 + c0], W[2 * C1 + c0 + 1])),
            __longlong_as_double(pk(W[3 * C1 + c0], W[3 * C1 + c0 + 1])));
        Bp[t] = pk(b[c0], b[c0 + 1]);
    }
    if (t == 0) xn = x[n];
    __syncthreads();
    int beg = g_off[n], end = g_off[n + 1];
    u64 acc2[P1];
#pragma unroll
    for (int o = 0; o < P1; o++) acc2[o] = 0ull;
    for (int p = beg + t; p < end; p += 256) {
        int p2 = p + 128;
        bool has2 = p2 < end;
        float4 aA = g_ea[p];
        float4 aB = has2 ? g_ea[p2] : aA;
        float xsA = __ldg(x + g_ssrc[p]);
        float xsB = has2 ? __ldg(x + g_ssrc[p2]) : 0.f;
        u64 axA = pk(aA.x, aA.x), ayA = pk(aA.y, aA.y), azA = pk(aA.z, aA.z), awA = pk(aA.w, aA.w);
        u64 axB = pk(aB.x, aB.x), ayB = pk(aB.y, aB.y), azB = pk(aB.z, aB.z), awB = pk(aB.w, aB.w);
        u64 xiA = pk(xsA, xsA), xiB = pk(xsB, xsB);
#pragma unroll
        for (int op = 0; op < P1; op++) {
            double2 d0 = Wp[op][0];
            double2 d1 = Wp[op][1];
            u64 vA = fma2(axA, d2u(d0.x), Bp[op]);
            vA = fma2(ayA, d2u(d0.y), vA);
            vA = fma2(azA, d2u(d1.x), vA);
            vA = fma2(awA, d2u(d1.y), vA);
            acc2[op] = fma2(xiA, relu2(vA), acc2[op]);
            u64 vB = fma2(axB, d2u(d0.x), Bp[op]);
            vB = fma2(ayB, d2u(d0.y), vB);
            vB = fma2(azB, d2u(d1.x), vB);
            vB = fma2(awB, d2u(d1.y), vB);
            acc2[op] = fma2(xiB, relu2(vB), acc2[op]);
        }
    }
    float acc[C1];
#pragma unroll
    for (int op = 0; op < P1; op++) upk(acc2[op], acc[2 * op], acc[2 * op + 1]);
#pragma unroll
    for (int o = 0; o < C1; o++)
#pragma unroll
        for (int off = 16; off; off >>= 1)
            acc[o] += __shfl_down_sync(0xffffffffu, acc[o], off);
    int wid = t >> 5, lane = t & 31;
    if (lane == 0)
#pragma unroll
        for (int o = 0; o < C1; o++) parts[wid][o] = acc[o];
    __syncthreads();
    if (t < C1) {
        float s = parts[0][t] + parts[1][t] + parts[2][t] + parts[3][t];
        float cnt = fmaxf((float)(end - beg), 1.f);
        float v = s / cnt + bias[t] + xn * root[t];
        g_h1[n * C1 + t] = fmaxf(v, 0.f);
    }
}

// ---------------- layer 2: cin=36, cout=24, packed, 2-edge, 128 thr (R12 config) ----------------
#define P2 (C2 / 2)
#define W2PAIRS (C1 * P2)
__global__ __launch_bounds__(128, 4) void k_layer2(
    const float* __restrict__ W, const float* __restrict__ b,
    const float* __restrict__ root, const float* __restrict__ bias)
{
    __shared__ double2 WpA[W2PAIRS][2];
    __shared__ u64 WpB[W2PAIRS];
    __shared__ float hprev[C1];
    __shared__ float rootS[C1 * C2];
    __shared__ float parts[4][C2];
    int n = blockIdx.x, t = threadIdx.x;
    for (int idx = t; idx < W2PAIRS; idx += 128) {
        int i = idx / P2, op = idx % P2;
        int c0 = i * C2 + 2 * op;
        WpA[idx][0] = make_double2(
            __longlong_as_double(pk(W[c0], W[c0 + 1])),
            __longlong_as_double(pk(W[864 + c0], W[864 + c0 + 1])));
        WpA[idx][1] = make_double2(
            __longlong_as_double(pk(W[1728 + c0], W[1728 + c0 + 1])),
            __longlong_as_double(pk(W[2592 + c0], W[2592 + c0 + 1])));
        WpB[idx] = pk(b[c0], b[c0 + 1]);
    }
    if (t < C1) hprev[t] = g_h1[n * C1 + t];
    for (int idx = t; idx < C1 * C2; idx += 128) rootS[idx] = root[idx];
    __syncthreads();
    int beg = g_off[n], end = g_off[n + 1];
    u64 acc2[P2];
#pragma unroll
    for (int o = 0; o < P2; o++) acc2[o] = 0ull;
    for (int p = beg + t; p < end; p += 256) {
        int p2 = p + 128;
        bool has2 = p2 < end;
        float4 aA = g_ea[p];
        float4 aB = has2 ? g_ea[p2] : aA;
        int srcA = g_ssrc[p];
        int srcB = has2 ? g_ssrc[p2] : srcA;
        float mB = has2 ? 1.f : 0.f;
        u64 axA = pk(aA.x, aA.x), ayA = pk(aA.y, aA.y), azA = pk(aA.z, aA.z), awA = pk(aA.w, aA.w);
        u64 axB = pk(aB.x, aB.x), ayB = pk(aB.y, aB.y), azB = pk(aB.z, aB.z), awB = pk(aB.w, aB.w);
        const float4* hpA = (const float4*)(g_h1 + srcA * C1);
        const float4* hpB = (const float4*)(g_h1 + srcB * C1);
#pragma unroll 1
        for (int q = 0; q < C1 / 4; q++) {
            float4 vA = __ldg(hpA + q);
            float4 vB = __ldg(hpB + q);
            float fa[4] = {vA.x, vA.y, vA.z, vA.w};
            float fb[4] = {vB.x * mB, vB.y * mB, vB.z * mB, vB.w * mB};
#pragma unroll
            for (int j = 0; j < 4; j++) {
                int base = (4 * q + j) * P2;
                u64 xiA = pk(fa[j], fa[j]);
                u64 xiB = pk(fb[j], fb[j]);
#pragma unroll
                for (int op = 0; op < P2; op++) {
                    double2 d0 = WpA[base + op][0];
                    double2 d1 = WpA[base + op][1];
                    u64 vvA = fma2(axA, d2u(d0.x), WpB[base + op]);
                    vvA = fma2(ayA, d2u(d0.y), vvA);
                    vvA = fma2(azA, d2u(d1.x), vvA);
                    vvA = fma2(awA, d2u(d1.y), vvA);
                    acc2[op] = fma2(xiA, relu2(vvA), acc2[op]);
                    u64 vvB = fma2(axB, d2u(d0.x), WpB[base + op]);
                    vvB = fma2(ayB, d2u(d0.y), vvB);
                    vvB = fma2(azB, d2u(d1.x), vvB);
                    vvB = fma2(awB, d2u(d1.y), vvB);
                    acc2[op] = fma2(xiB, relu2(vvB), acc2[op]);
                }
            }
        }
    }
    float acc[C2];
#pragma unroll
    for (int op = 0; op < P2; op++) upk(acc2[op], acc[2 * op], acc[2 * op + 1]);
#pragma unroll
    for (int o = 0; o < C2; o++)
#pragma unroll
        for (int off = 16; off; off >>= 1)
            acc[o] += __shfl_down_sync(0xffffffffu, acc[o], off);
    int wid = t >> 5, lane = t & 31;
    if (lane == 0)
#pragma unroll
        for (int o = 0; o < C2; o++) parts[wid][o] = acc[o];
    __syncthreads();
    if (t < C2) {
        float s = parts[0][t] + parts[1][t] + parts[2][t] + parts[3][t];
        float cnt = fmaxf((float)(end - beg), 1.f);
        float v = s / cnt + bias[t];
#pragma unroll
        for (int i = 0; i < C1; i++) v = fmaf(hprev[i], rootS[i * C2 + t], v);
        g_h2[n * C2 + t] = fmaxf(v, 0.f);
    }
}

// ---------------- layer 3: cin=24, cout=8, packed, 2-edge, 128 thr (R12 config) ----------------
#define P3 (C3 / 2)
#define W3PAIRS (C2 * P3)
__global__ __launch_bounds__(128, 4) void k_layer3(
    const float* __restrict__ W, const float* __restrict__ b,
    const float* __restrict__ root, const float* __restrict__ bias)
{
    __shared__ double2 WpA[W3PAIRS][2];
    __shared__ u64 WpB[W3PAIRS];
    __shared__ float hprev[C2];
    __shared__ float rootS[C2 * C3];
    __shared__ float parts[4][C3];
    int n = blockIdx.x, t = threadIdx.x;
    if (t < W3PAIRS) {
        int i = t / P3, op = t % P3;
        int c0 = i * C3 + 2 * op;
        WpA[t][0] = make_double2(
            __longlong_as_double(pk(W[c0], W[c0 + 1])),
            __longlong_as_double(pk(W[192 + c0], W[192 + c0 + 1])));
        WpA[t][1] = make_double2(
            __longlong_as_double(pk(W[384 + c0], W[384 + c0 + 1])),
            __longlong_as_double(pk(W[576 + c0], W[576 + c0 + 1])));
        WpB[t] = pk(b[c0], b[c0 + 1]);
    }
    if (t < C2) hprev[t] = g_h2[n * C2 + t];
    for (int idx = t; idx < C2 * C3; idx += 128) rootS[idx] = root[idx];
    __syncthreads();
    int beg = g_off[n], end = g_off[n + 1];
    u64 acc2[P3];
#pragma unroll
    for (int o = 0; o < P3; o++) acc2[o] = 0ull;
    for (int p = beg + t; p < end; p += 256) {
        int p2 = p + 128;
        bool has2 = p2 < end;
        float4 aA = g_ea[p];
        float4 aB = has2 ? g_ea[p2] : aA;
        int srcA = g_ssrc[p];
        int srcB = has2 ? g_ssrc[p2] : srcA;
        float mB = has2 ? 1.f : 0.f;
        u64 axA = pk(aA.x, aA.x), ayA = pk(aA.y, aA.y), azA = pk(aA.z, aA.z), awA = pk(aA.w, aA.w);
        u64 axB = pk(aB.x, aB.x), ayB = pk(aB.y, aB.y), azB = pk(aB.z, aB.z), awB = pk(aB.w, aB.w);
        const float4* hpA = (const float4*)(g_h2 + srcA * C2);
        const float4* hpB = (const float4*)(g_h2 + srcB * C2);
#pragma unroll 1
        for (int q = 0; q < C2 / 4; q++) {
            float4 vA = __ldg(hpA + q);
            float4 vB = __ldg(hpB + q);
            float fa[4] = {vA.x, vA.y, vA.z, vA.w};
            float fb[4] = {vB.x * mB, vB.y * mB, vB.z * mB, vB.w * mB};
#pragma unroll
            for (int j = 0; j < 4; j++) {
                int base = (4 * q + j) * P3;
                u64 xiA = pk(fa[j], fa[j]);
                u64 xiB = pk(fb[j], fb[j]);
#pragma unroll
                for (int op = 0; op < P3; op++) {
                    double2 d0 = WpA[base + op][0];
                    double2 d1 = WpA[base + op][1];
                    u64 vvA = fma2(axA, d2u(d0.x), WpB[base + op]);
                    vvA = fma2(ayA, d2u(d0.y), vvA);
                    vvA = fma2(azA, d2u(d1.x), vvA);
                    vvA = fma2(awA, d2u(d1.y), vvA);
                    acc2[op] = fma2(xiA, relu2(vvA), acc2[op]);
                    u64 vvB = fma2(axB, d2u(d0.x), WpB[base + op]);
                    vvB = fma2(ayB, d2u(d0.y), vvB);
                    vvB = fma2(azB, d2u(d1.x), vvB);
                    vvB = fma2(awB, d2u(d1.y), vvB);
                    acc2[op] = fma2(xiB, relu2(vvB), acc2[op]);
                }
            }
        }
    }
    float acc[C3];
#pragma unroll
    for (int op = 0; op < P3; op++) upk(acc2[op], acc[2 * op], acc[2 * op + 1]);
#pragma unroll
    for (int o = 0; o < C3; o++)
#pragma unroll
        for (int off = 16; off; off >>= 1)
            acc[o] += __shfl_down_sync(0xffffffffu, acc[o], off);
    int wid = t >> 5, lane = t & 31;
    if (lane == 0)
#pragma unroll
        for (int o = 0; o < C3; o++) parts[wid][o] = acc[o];
    __syncthreads();
    if (t < C3) {
        float s = parts[0][t] + parts[1][t] + parts[2][t] + parts[3][t];
        float cnt = fmaxf((float)(end - beg), 1.f);
        float v = s / cnt + bias[t];
#pragma unroll
        for (int i = 0; i < C2; i++) v = fmaf(hprev[i], rootS[i * C3 + t], v);
        g_h3[n * C3 + t] = fmaxf(v, 0.f);
    }
}

// ---------------- CBT: out[i,j] = sum_d |h3[j,d]-h3[i,d]| ----------------
__global__ void k_cbt(float* __restrict__ out) {
    __shared__ float hs[NN * C3];
    int t = threadIdx.x;
    for (int idx = t; idx < NN * C3; idx += blockDim.x) hs[idx] = g_h3[idx];
    __syncthreads();
    int i = blockIdx.x;
    float hi[C3];
#pragma unroll
    for (int d = 0; d < C3; d++) hi[d] = hs[i * C3 + d];
    float s = 0.f;
#pragma unroll
    for (int d = 0; d < C3; d++) s += fabsf(hs[t * C3 + d] - hi[d]);
    out[i * NN + t] = s;
}

extern "C" void kernel_launch(void* const* d_in, const int* in_sizes, int n_in,
                              void* d_out, int out_size) {
    const float* x  = (const float*)d_in[0];
    const float4* ea = (const float4*)d_in[1];
    const void* ei = d_in[2];
    const float* W1 = (const float*)d_in[3];
    const float* b1 = (const float*)d_in[4];
    const float* r1 = (const float*)d_in[5];
    const float* B1 = (const float*)d_in[6];
    const float* W2 = (const float*)d_in[7];
    const float* b2 = (const float*)d_in[8];
    const float* r2 = (const float*)d_in[9];
    const float* B2 = (const float*)d_in[10];
    const float* W3 = (const float*)d_in[11];
    const float* b3 = (const float*)d_in[12];
    const float* r3 = (const float*)d_in[13];
    const float* B3 = (const float*)d_in[14];
    float* out = (float*)d_out;

    int E = in_sizes[2] / 2;
    if (E > EMAX) E = EMAX;
    int EB = (E + EPB - 1) / EPB;

    k_bhist<<<EB, 256>>>(ei, E, EB);
    k_bscan<<<NN, 256>>>(EB);
    k_place<<<EB, 256>>>(ei, ea, E, EB);

    k_layer1<<<NN, 128>>>(x, W1, b1, r1, B1);
    k_layer2<<<NN, 128>>>(W2, b2, r2, B2);
    k_layer3<<<NN, 128>>>(W3, b3, r3, B3);

    k_cbt<<<NN, NN>>>(out);
}